// round 9
// baseline (speedup 1.0000x reference)
#include <cuda_runtime.h>
#include <cstdint>
#include <cstddef>

// ---------------------------------------------------------------------------
// SimultaneousRetrievalModel on GB300 (sm_103a)
// Persistent blocks (1/SM), warp = 4 rows, all weights in smem (odd strides),
// f32x2 packed FMA (rows paired) for down-proj / up-proj / classifier.
// R8: fix input-pointer order (per-tier interleaved Wp,bp,Wu,bu), drop static guard.
// ---------------------------------------------------------------------------

#define WARPS 12
#define NTHR  (WARPS * 32)
#define NB    152

typedef unsigned long long u64;

__device__ __forceinline__ u64 pack2(float lo, float hi) {
    u64 r; asm("mov.b64 %0, {%1, %2};" : "=l"(r) : "f"(lo), "f"(hi)); return r;
}
__device__ __forceinline__ void unpack2(u64 v, float& lo, float& hi) {
    asm("mov.b64 {%0, %1}, %2;" : "=f"(lo), "=f"(hi) : "l"(v));
}
__device__ __forceinline__ u64 fma2(u64 a, u64 b, u64 c) {
    u64 d; asm("fma.rn.f32x2 %0, %1, %2, %3;" : "=l"(d) : "l"(a), "l"(b), "l"(c)); return d;
}

// ---- smem layout (float offsets) ----
// Wp_s  [112][65] : rows pre-scaled by 1/sqrt(dim)
// bp_s  [112]     : pre-scaled
// Wu_s  [64][113] : Wu concatenated over tiers along j
// bu_s  [3][64]
// Wc_s  [64][65]
// bc_s  [64]
// per-warp scratch (stride 1664 floats)
#define OFF_WP   0
#define OFF_BP   7280
#define OFF_WU   7392
#define OFF_BU   14624
#define OFF_WC   14816
#define OFF_BC   18976
#define OFF_WARP 19040
#define W_STRIDE 1664
#define SMEM_FLOATS (OFF_WARP + WARPS * W_STRIDE)
#define SMEM_BYTES  (SMEM_FLOATS * 4)

__global__ void __launch_bounds__(NTHR, 1) retrieval_kernel(
    const float* __restrict__ q_g,
    const float* __restrict__ m0_g,
    const float* __restrict__ m1_g,
    const float* __restrict__ m2_g,
    const float* __restrict__ Wp0, const float* __restrict__ bp0,
    const float* __restrict__ Wp1, const float* __restrict__ bp1,
    const float* __restrict__ Wp2, const float* __restrict__ bp2,
    const float* __restrict__ Wu0, const float* __restrict__ bu0,
    const float* __restrict__ Wu1, const float* __restrict__ bu1,
    const float* __restrict__ Wu2, const float* __restrict__ bu2,
    const float* __restrict__ Wc_g, const float* __restrict__ bc_g,
    float* __restrict__ out_g,
    int nrows)
{
    extern __shared__ float sm[];
    const int tid  = threadIdx.x;
    const int wid  = tid >> 5;
    const int lane = tid & 31;

    // ---------------- stage weights (once per block) ----------------
    {
        const float s0 = 0.125f;                  // 1/sqrt(64)
        const float s1 = 0.17677669529663687f;    // 1/sqrt(32)
        const float s2 = 0.25f;                   // 1/sqrt(16)
        for (int idx = tid; idx < 112 * 64; idx += NTHR) {
            int j = idx >> 6, h = idx & 63;
            float v;
            if (j < 64)      v = Wp0[j * 64 + h] * s0;
            else if (j < 96) v = Wp1[(j - 64) * 64 + h] * s1;
            else             v = Wp2[(j - 96) * 64 + h] * s2;
            sm[OFF_WP + j * 65 + h] = v;
        }
        for (int j = tid; j < 112; j += NTHR) {
            float v;
            if (j < 64)      v = bp0[j] * s0;
            else if (j < 96) v = bp1[j - 64] * s1;
            else             v = bp2[j - 96] * s2;
            sm[OFF_BP + j] = v;
        }
        for (int idx = tid; idx < 64 * 112; idx += NTHR) {
            int h = idx / 112, j = idx - h * 112;
            float v;
            if (j < 64)      v = Wu0[h * 64 + j];
            else if (j < 96) v = Wu1[h * 32 + (j - 64)];
            else             v = Wu2[h * 16 + (j - 96)];
            sm[OFF_WU + h * 113 + j] = v;
        }
        for (int idx = tid; idx < 192; idx += NTHR) {
            int i = idx >> 6, h = idx & 63;
            sm[OFF_BU + idx] = (i == 0) ? bu0[h] : (i == 1) ? bu1[h] : bu2[h];
        }
        for (int idx = tid; idx < 64 * 64; idx += NTHR) {
            int o = idx >> 6, h = idx & 63;
            sm[OFF_WC + o * 65 + h] = Wc_g[idx];
        }
        for (int idx = tid; idx < 64; idx += NTHR) sm[OFF_BC + idx] = bc_g[idx];
    }
    __syncthreads();

    float* wbase  = sm + OFF_WARP + wid * W_STRIDE;
    float* q_s    = wbase;          // [4][64]
    float* qp_s   = wbase + 256;    // [4][112]
    float* sims_s = wbase + 704;    // [4][28]
    float* w_s    = wbase + 816;    // [4][28]
    float* conf_s = wbase + 928;    // [4][3]
    float* c_s    = wbase + 940;    // [4][3]
    float* rvp    = wbase + 952;    // [2][112][2]  (8B aligned)
    float* hidp   = wbase + 1400;   // [2][64][2]   (8B aligned)

    const float* Wp_s = sm + OFF_WP;
    const float* bp_s = sm + OFF_BP;
    const float* Wu_s = sm + OFF_WU;
    const float* bu_s = sm + OFF_BU;
    const float* Wc_s = sm + OFF_WC;
    const float* bc_s = sm + OFF_BC;

    const int gw = blockIdx.x * WARPS + wid;
    const int ngroups = (nrows + 3) >> 2;
    const int gstride = gridDim.x * WARPS;

    for (int g = gw; g < ngroups; g += gstride) {
        const int r0 = g * 4;

        // ---- load q for 4 rows ----
        #pragma unroll
        for (int r = 0; r < 4; r++) {
            int row = min(r0 + r, nrows - 1);
            q_s[r * 64 + lane]      = q_g[(size_t)row * 64 + lane];
            q_s[r * 64 + lane + 32] = q_g[(size_t)row * 64 + lane + 32];
        }
        __syncwarp();

        // ---- step A: down-proj, qp[j] = scaled(q.Wp^T + bp), j-slots per lane ----
        {
            int j3 = (lane < 16) ? (lane + 96) : (lane + 64);  // dup for lanes>=16
            int js[4] = { lane, lane + 32, lane + 64, j3 };
            u64 aA[4], aB[4];   // pair0 = rows(0,1), pair1 = rows(2,3)
            #pragma unroll
            for (int k = 0; k < 4; k++) {
                float b = bp_s[js[k]];
                aA[k] = pack2(b, b);
                aB[k] = pack2(b, b);
            }
            #pragma unroll 4
            for (int h = 0; h < 64; h++) {
                u64 qa = pack2(q_s[h],       q_s[64 + h]);
                u64 qb = pack2(q_s[128 + h], q_s[192 + h]);
                #pragma unroll
                for (int k = 0; k < 4; k++) {
                    float w = Wp_s[js[k] * 65 + h];
                    u64 ww = pack2(w, w);
                    aA[k] = fma2(ww, qa, aA[k]);
                    aB[k] = fma2(ww, qb, aB[k]);
                }
            }
            #pragma unroll
            for (int k = 0; k < 4; k++) {
                if (k == 3 && lane >= 16) break;
                float v0, v1, v2, v3;
                unpack2(aA[k], v0, v1);
                unpack2(aB[k], v2, v3);
                qp_s[0 * 112 + js[k]] = v0;
                qp_s[1 * 112 + js[k]] = v1;
                qp_s[2 * 112 + js[k]] = v2;
                qp_s[3 * 112 + js[k]] = v3;
            }
        }
        __syncwarp();

        // ---- step B: sims (112 tasks = 4 rows x 28 slots) ----
        for (int t = lane; t < 112; t += 32) {
            int r = t / 28, s = t - r * 28;
            int row = min(r0 + r, nrows - 1);
            const float* mp; int dim, j0;
            if (s < 4)       { mp = m0_g + (size_t)row * 256 + s * 64;        dim = 64; j0 = 0;  }
            else if (s < 12) { mp = m1_g + (size_t)row * 256 + (s - 4) * 32;  dim = 32; j0 = 64; }
            else             { mp = m2_g + (size_t)row * 256 + (s - 12) * 16; dim = 16; j0 = 96; }
            const float* qp = &qp_s[r * 112 + j0];
            float acc = 0.f;
            #pragma unroll 4
            for (int h = 0; h < dim; h++) acc += mp[h] * qp[h];
            sims_s[r * 28 + s] = acc;
        }
        __syncwarp();

        // ---- step C: per-tier softmax; conf = max weight = 1/sum(exp) ----
        if (lane < 12) {
            int r = lane / 3, i = lane - r * 3;
            int sb  = (i == 0) ? 0 : (i == 1) ? 4 : 12;
            int cnt = (i == 0) ? 4 : (i == 1) ? 8 : 16;
            const float* sp = &sims_s[r * 28 + sb];
            float mx = -1e30f;
            for (int s = 0; s < cnt; s++) mx = fmaxf(mx, sp[s]);
            float sum = 0.f;
            float* wp = &w_s[r * 28 + sb];
            for (int s = 0; s < cnt; s++) { float e = __expf(sp[s] - mx); wp[s] = e; sum += e; }
            float inv = 1.f / sum;
            for (int s = 0; s < cnt; s++) wp[s] *= inv;
            conf_s[r * 3 + i] = inv;   // max softmax weight
        }
        __syncwarp();

        // ---- step D: conf softmax over 3 tiers per row ----
        if (lane < 4) {
            int r = lane;
            float c0 = conf_s[r * 3], c1 = conf_s[r * 3 + 1], c2 = conf_s[r * 3 + 2];
            float m = fmaxf(c0, fmaxf(c1, c2));
            float e0 = __expf(c0 - m), e1 = __expf(c1 - m), e2 = __expf(c2 - m);
            float inv = 1.f / (e0 + e1 + e2);
            c_s[r * 3]     = e0 * inv;
            c_s[r * 3 + 1] = e1 * inv;
            c_s[r * 3 + 2] = e2 * inv;
        }
        __syncwarp();

        // ---- step E: retrieved (scaled by c), pair-packed into rvp ----
        #pragma unroll
        for (int r = 0; r < 4; r++) {
            int row = min(r0 + r, nrows - 1);
            const float* wr = &w_s[r * 28];
            float c0 = c_s[r * 3], c1 = c_s[r * 3 + 1], c2 = c_s[r * 3 + 2];
            int pbase = (r >> 1) * 224, sub = (r & 1);
            const float* m0p = m0_g + (size_t)row * 256;
            #pragma unroll
            for (int jj = 0; jj < 2; jj++) {
                int j = lane + jj * 32;
                float a = 0.f;
                #pragma unroll
                for (int s = 0; s < 4; s++) a += wr[s] * m0p[s * 64 + j];
                rvp[pbase + j * 2 + sub] = c0 * a;
            }
            const float* m1p = m1_g + (size_t)row * 256;
            {
                float a = 0.f;
                #pragma unroll
                for (int s = 0; s < 8; s++) a += wr[4 + s] * m1p[s * 32 + lane];
                rvp[pbase + (64 + lane) * 2 + sub] = c1 * a;
            }
            if (lane < 16) {
                const float* m2p = m2_g + (size_t)row * 256;
                float a = 0.f;
                #pragma unroll
                for (int s = 0; s < 16; s++) a += wr[12 + s] * m2p[s * 16 + lane];
                rvp[pbase + (96 + lane) * 2 + sub] = c2 * a;
            }
        }
        __syncwarp();

        // ---- step F: up-proj, hid[h] = Wu_cat . rv + sum_i c_i*bu_i[h] ----
        {
            u64 cp0[3], cp1[3];
            #pragma unroll
            for (int i = 0; i < 3; i++) {
                cp0[i] = pack2(c_s[i],     c_s[3 + i]);
                cp1[i] = pack2(c_s[6 + i], c_s[9 + i]);
            }
            #pragma unroll
            for (int hs = 0; hs < 2; hs++) {
                int h = lane + hs * 32;
                u64 aP0 = 0, aP1 = 0;
                #pragma unroll
                for (int i = 0; i < 3; i++) {
                    float bv = bu_s[i * 64 + h];
                    u64 bb = pack2(bv, bv);
                    aP0 = fma2(cp0[i], bb, aP0);
                    aP1 = fma2(cp1[i], bb, aP1);
                }
                const float* wrow = &Wu_s[h * 113];
                #pragma unroll 4
                for (int j = 0; j < 112; j++) {
                    float w = wrow[j];
                    u64 ww = pack2(w, w);
                    u64 rv0 = *(const u64*)&rvp[j * 2];
                    u64 rv1 = *(const u64*)&rvp[224 + j * 2];
                    aP0 = fma2(ww, rv0, aP0);
                    aP1 = fma2(ww, rv1, aP1);
                }
                *(u64*)&hidp[h * 2]       = aP0;
                *(u64*)&hidp[128 + h * 2] = aP1;
            }
        }
        __syncwarp();

        // ---- step G: classifier + store ----
        #pragma unroll
        for (int os = 0; os < 2; os++) {
            int o = lane + os * 32;
            float b = bc_s[o];
            u64 aP0 = pack2(b, b), aP1 = pack2(b, b);
            const float* wrow = &Wc_s[o * 65];
            #pragma unroll 4
            for (int h = 0; h < 64; h++) {
                float w = wrow[h];
                u64 ww = pack2(w, w);
                aP0 = fma2(ww, *(const u64*)&hidp[h * 2], aP0);
                aP1 = fma2(ww, *(const u64*)&hidp[128 + h * 2], aP1);
            }
            float v0, v1, v2, v3;
            unpack2(aP0, v0, v1);
            unpack2(aP1, v2, v3);
            if (r0 < nrows)     out_g[(size_t)r0 * 64 + o]       = v0;
            if (r0 + 1 < nrows) out_g[(size_t)(r0 + 1) * 64 + o] = v1;
            if (r0 + 2 < nrows) out_g[(size_t)(r0 + 2) * 64 + o] = v2;
            if (r0 + 3 < nrows) out_g[(size_t)(r0 + 3) * 64 + o] = v3;
        }
        __syncwarp();
    }
}

extern "C" void kernel_launch(void* const* d_in, const int* in_sizes, int n_in,
                              void* d_out, int out_size) {
    // metadata order (setup_inputs insertion order — per-tier INTERLEAVED):
    // 0:query_h 1:mem0 2:mem1 3:mem2
    // 4:Wp0 5:bp0 6:Wu0 7:bu0
    // 8:Wp1 9:bp1 10:Wu1 11:bu1
    // 12:Wp2 13:bp2 14:Wu2 15:bu2
    // 16:Wc 17:bc
    const float* q   = (const float*)d_in[0];
    const float* m0  = (const float*)d_in[1];
    const float* m1  = (const float*)d_in[2];
    const float* m2  = (const float*)d_in[3];
    const float* Wp0 = (const float*)d_in[4];
    const float* bp0 = (const float*)d_in[5];
    const float* Wu0 = (const float*)d_in[6];
    const float* bu0 = (const float*)d_in[7];
    const float* Wp1 = (const float*)d_in[8];
    const float* bp1 = (const float*)d_in[9];
    const float* Wu1 = (const float*)d_in[10];
    const float* bu1 = (const float*)d_in[11];
    const float* Wp2 = (const float*)d_in[12];
    const float* bp2 = (const float*)d_in[13];
    const float* Wu2 = (const float*)d_in[14];
    const float* bu2 = (const float*)d_in[15];
    const float* Wc  = (const float*)d_in[16];
    const float* bc  = (const float*)d_in[17];
    float* out = (float*)d_out;

    int nrows = in_sizes[0] / 64;

    cudaFuncSetAttribute(retrieval_kernel,
                         cudaFuncAttributeMaxDynamicSharedMemorySize, SMEM_BYTES);

    retrieval_kernel<<<NB, NTHR, SMEM_BYTES>>>(
        q, m0, m1, m2,
        Wp0, bp0, Wp1, bp1, Wp2, bp2,
        Wu0, bu0, Wu1, bu1, Wu2, bu2,
        Wc, bc, out, nrows);
}

// round 11
// speedup vs baseline: 1.9452x; 1.9452x over previous
#include <cuda_runtime.h>
#include <cstdint>
#include <cstddef>

// ---------------------------------------------------------------------------
// SimultaneousRetrievalModel on GB300 (sm_103a)
// R10/R11: kill L1TEX divergence. Mem tiles loaded once via LDG.128 into padded
// smem; sims via lane-split + shfl_xor reductions (softmax fused); retrieved
// from smem. A/F/G loop-reordered to hoist broadcast LDS (6->4 LDS per iter).
// (R11 = identical resubmit; R10 bench died to container infra failure.)
// ---------------------------------------------------------------------------

#define WARPS 12
#define NTHR  (WARPS * 32)
#define NB    152

typedef unsigned long long u64;

__device__ __forceinline__ u64 pack2(float lo, float hi) {
    u64 r; asm("mov.b64 %0, {%1, %2};" : "=l"(r) : "f"(lo), "f"(hi)); return r;
}
__device__ __forceinline__ void unpack2(u64 v, float& lo, float& hi) {
    asm("mov.b64 {%0, %1}, %2;" : "=f"(lo), "=f"(hi) : "l"(v));
}
__device__ __forceinline__ u64 fma2(u64 a, u64 b, u64 c) {
    u64 d; asm("fma.rn.f32x2 %0, %1, %2, %3;" : "=l"(d) : "l"(a), "l"(b), "l"(c)); return d;
}

// ---- block-shared weights (float offsets) ----
#define OFF_WP   0        // [112][65] rows pre-scaled by 1/sqrt(dim)
#define OFF_BP   7280     // [112] pre-scaled
#define OFF_WU   7392     // [64][113] Wu concat over tiers along j
#define OFF_BU   14624    // [3][64]
#define OFF_WC   14816    // [64][65]
#define OFF_BC   18976    // [64]
#define OFF_WARP 19040

// ---- per-warp scratch (float offsets within warp region) ----
#define S_QT   0        // [64][6]  q transposed (rows r at +0..3)            384
#define S_QP   384      // [4][112] down-projected queries                    448
#define S_M0   832      // [4][65]  tier0 mem (padded)                        264
#define S_M1   1096     // [8][33]  tier1 mem                                 264
#define S_M2   1360     // [16][17] tier2 mem                                 272
#define S_W    1632     // [28] tier softmax weights (current row)             32
#define S_C    1664     // [4][3] conf-softmax coeffs                          16
#define S_RVP  1680     // [2][112][2] retrieved, pair-packed (8B aligned)    448
#define S_HID  2128     // [2][64][2] hidden, pair-packed (8B aligned)        256
#define W_STRIDE 2384

#define SMEM_FLOATS (OFF_WARP + WARPS * W_STRIDE)
#define SMEM_BYTES  (SMEM_FLOATS * 4)

__global__ void __launch_bounds__(NTHR, 1) retrieval_kernel(
    const float* __restrict__ q_g,
    const float* __restrict__ m0_g,
    const float* __restrict__ m1_g,
    const float* __restrict__ m2_g,
    const float* __restrict__ Wp0, const float* __restrict__ bp0,
    const float* __restrict__ Wp1, const float* __restrict__ bp1,
    const float* __restrict__ Wp2, const float* __restrict__ bp2,
    const float* __restrict__ Wu0, const float* __restrict__ bu0,
    const float* __restrict__ Wu1, const float* __restrict__ bu1,
    const float* __restrict__ Wu2, const float* __restrict__ bu2,
    const float* __restrict__ Wc_g, const float* __restrict__ bc_g,
    float* __restrict__ out_g,
    int nrows)
{
    extern __shared__ float sm[];
    const int tid  = threadIdx.x;
    const int wid  = tid >> 5;
    const int lane = tid & 31;

    // ---------------- stage weights (once per block) ----------------
    {
        const float s0 = 0.125f;                  // 1/sqrt(64)
        const float s1 = 0.17677669529663687f;    // 1/sqrt(32)
        const float s2 = 0.25f;                   // 1/sqrt(16)
        for (int idx = tid; idx < 112 * 64; idx += NTHR) {
            int j = idx >> 6, h = idx & 63;
            float v;
            if (j < 64)      v = Wp0[j * 64 + h] * s0;
            else if (j < 96) v = Wp1[(j - 64) * 64 + h] * s1;
            else             v = Wp2[(j - 96) * 64 + h] * s2;
            sm[OFF_WP + j * 65 + h] = v;
        }
        for (int j = tid; j < 112; j += NTHR) {
            float v;
            if (j < 64)      v = bp0[j] * s0;
            else if (j < 96) v = bp1[j - 64] * s1;
            else             v = bp2[j - 96] * s2;
            sm[OFF_BP + j] = v;
        }
        for (int idx = tid; idx < 64 * 112; idx += NTHR) {
            int h = idx / 112, j = idx - h * 112;
            float v;
            if (j < 64)      v = Wu0[h * 64 + j];
            else if (j < 96) v = Wu1[h * 32 + (j - 64)];
            else             v = Wu2[h * 16 + (j - 96)];
            sm[OFF_WU + h * 113 + j] = v;
        }
        for (int idx = tid; idx < 192; idx += NTHR) {
            int i = idx >> 6, h = idx & 63;
            sm[OFF_BU + idx] = (i == 0) ? bu0[h] : (i == 1) ? bu1[h] : bu2[h];
        }
        for (int idx = tid; idx < 64 * 64; idx += NTHR) {
            int o = idx >> 6, h = idx & 63;
            sm[OFF_WC + o * 65 + h] = Wc_g[idx];
        }
        for (int idx = tid; idx < 64; idx += NTHR) sm[OFF_BC + idx] = bc_g[idx];
    }
    __syncthreads();

    float* wbase = sm + OFF_WARP + wid * W_STRIDE;
    float* qt    = wbase + S_QT;
    float* qp_s  = wbase + S_QP;
    float* mem0  = wbase + S_M0;
    float* mem1  = wbase + S_M1;
    float* mem2  = wbase + S_M2;
    float* w_s   = wbase + S_W;
    float* c_s   = wbase + S_C;
    float* rvp   = wbase + S_RVP;
    float* hidp  = wbase + S_HID;

    const float* Wp_s = sm + OFF_WP;
    const float* bp_s = sm + OFF_BP;
    const float* Wu_s = sm + OFF_WU;
    const float* bu_s = sm + OFF_BU;
    const float* Wc_s = sm + OFF_WC;
    const float* bc_s = sm + OFF_BC;

    const int gw = blockIdx.x * WARPS + wid;
    const int ngroups = (nrows + 3) >> 2;
    const int gstride = gridDim.x * WARPS;

    for (int g = gw; g < ngroups; g += gstride) {
        const int r0 = g * 4;

        // ---- load q for 4 rows, transposed: qt[h*6 + r] ----
        #pragma unroll
        for (int r = 0; r < 4; r++) {
            int row = min(r0 + r, nrows - 1);
            float v1 = q_g[(size_t)row * 64 + lane];
            float v2 = q_g[(size_t)row * 64 + lane + 32];
            qt[lane * 6 + r]        = v1;
            qt[(lane + 32) * 6 + r] = v2;
        }
        __syncwarp();

        // ---- step A: down-proj, qp[j] = scaled(q.Wp^T + bp) ----
        {
            int j3 = (lane < 16) ? (lane + 96) : (lane + 64);  // dup lanes>=16
            int js[4] = { lane, lane + 32, lane + 64, j3 };
            u64 aA[4], aB[4];   // pair (row0,row1) / (row2,row3)
            #pragma unroll
            for (int k = 0; k < 4; k++) {
                float b = bp_s[js[k]];
                aA[k] = pack2(b, b);
                aB[k] = pack2(b, b);
            }
            #pragma unroll 4
            for (int h = 0; h < 64; h++) {
                u64 qa = *(const u64*)&qt[h * 6];       // (row0,row1)
                u64 qb = *(const u64*)&qt[h * 6 + 2];   // (row2,row3)
                #pragma unroll
                for (int k = 0; k < 4; k++) {
                    float w = Wp_s[js[k] * 65 + h];
                    u64 ww = pack2(w, w);
                    aA[k] = fma2(ww, qa, aA[k]);
                    aB[k] = fma2(ww, qb, aB[k]);
                }
            }
            #pragma unroll
            for (int k = 0; k < 4; k++) {
                if (k == 3 && lane >= 16) break;
                float v0, v1, v2, v3;
                unpack2(aA[k], v0, v1);
                unpack2(aB[k], v2, v3);
                qp_s[0 * 112 + js[k]] = v0;
                qp_s[1 * 112 + js[k]] = v1;
                qp_s[2 * 112 + js[k]] = v2;
                qp_s[3 * 112 + js[k]] = v3;
            }
        }
        __syncwarp();

        // ---- steps B-E: sequential rows; mem staged once, coalesced ----
        for (int r = 0; r < 4; r++) {
            int row = min(r0 + r, nrows - 1);

            // stage 3 tiles (256 floats each) via LDG.128, padded smem
            const float4* f0 = (const float4*)(m0_g + (size_t)row * 256);
            const float4* f1 = (const float4*)(m1_g + (size_t)row * 256);
            const float4* f2 = (const float4*)(m2_g + (size_t)row * 256);
            #pragma unroll
            for (int k = 0; k < 2; k++) {
                int e4 = k * 32 + lane;
                float4 v;
                float* dst;
                v = f0[e4];
                dst = &mem0[(e4 >> 4) * 65 + (e4 & 15) * 4];
                dst[0] = v.x; dst[1] = v.y; dst[2] = v.z; dst[3] = v.w;
                v = f1[e4];
                dst = &mem1[(e4 >> 3) * 33 + (e4 & 7) * 4];
                dst[0] = v.x; dst[1] = v.y; dst[2] = v.z; dst[3] = v.w;
                v = f2[e4];
                dst = &mem2[(e4 >> 2) * 17 + (e4 & 3) * 4];
                dst[0] = v.x; dst[1] = v.y; dst[2] = v.z; dst[3] = v.w;
            }
            __syncwarp();

            const float* qpr = qp_s + r * 112;
            float conf0, conf1, conf2;

            // tier0: 4 slots x dim64; lane = (s<<3)|hg
            {
                int s = lane >> 3, hg = lane & 7;
                const float* mrow = &mem0[s * 65 + hg * 8];
                const float* qph  = &qpr[hg * 8];
                float acc = 0.f;
                #pragma unroll
                for (int k = 0; k < 8; k++) acc += mrow[k] * qph[k];
                acc += __shfl_xor_sync(0xffffffffu, acc, 1);
                acc += __shfl_xor_sync(0xffffffffu, acc, 2);
                acc += __shfl_xor_sync(0xffffffffu, acc, 4);
                float mx = acc;
                mx = fmaxf(mx, __shfl_xor_sync(0xffffffffu, mx, 8));
                mx = fmaxf(mx, __shfl_xor_sync(0xffffffffu, mx, 16));
                float e = __expf(acc - mx);
                float se = e;
                se += __shfl_xor_sync(0xffffffffu, se, 8);
                se += __shfl_xor_sync(0xffffffffu, se, 16);
                float inv = 1.f / se;
                if ((lane & 7) == 0) w_s[s] = e * inv;
                conf0 = inv;
            }
            // tier1: 8 slots x dim32; lane = (s<<2)|hg
            {
                int s = lane >> 2, hg = lane & 3;
                const float* mrow = &mem1[s * 33 + hg * 8];
                const float* qph  = &qpr[64 + hg * 8];
                float acc = 0.f;
                #pragma unroll
                for (int k = 0; k < 8; k++) acc += mrow[k] * qph[k];
                acc += __shfl_xor_sync(0xffffffffu, acc, 1);
                acc += __shfl_xor_sync(0xffffffffu, acc, 2);
                float mx = acc;
                mx = fmaxf(mx, __shfl_xor_sync(0xffffffffu, mx, 4));
                mx = fmaxf(mx, __shfl_xor_sync(0xffffffffu, mx, 8));
                mx = fmaxf(mx, __shfl_xor_sync(0xffffffffu, mx, 16));
                float e = __expf(acc - mx);
                float se = e;
                se += __shfl_xor_sync(0xffffffffu, se, 4);
                se += __shfl_xor_sync(0xffffffffu, se, 8);
                se += __shfl_xor_sync(0xffffffffu, se, 16);
                float inv = 1.f / se;
                if ((lane & 3) == 0) w_s[4 + s] = e * inv;
                conf1 = inv;
            }
            // tier2: 16 slots x dim16; lane = (s<<1)|hg
            {
                int s = lane >> 1, hg = lane & 1;
                const float* mrow = &mem2[s * 17 + hg * 8];
                const float* qph  = &qpr[96 + hg * 8];
                float acc = 0.f;
                #pragma unroll
                for (int k = 0; k < 8; k++) acc += mrow[k] * qph[k];
                acc += __shfl_xor_sync(0xffffffffu, acc, 1);
                float mx = acc;
                mx = fmaxf(mx, __shfl_xor_sync(0xffffffffu, mx, 2));
                mx = fmaxf(mx, __shfl_xor_sync(0xffffffffu, mx, 4));
                mx = fmaxf(mx, __shfl_xor_sync(0xffffffffu, mx, 8));
                mx = fmaxf(mx, __shfl_xor_sync(0xffffffffu, mx, 16));
                float e = __expf(acc - mx);
                float se = e;
                se += __shfl_xor_sync(0xffffffffu, se, 2);
                se += __shfl_xor_sync(0xffffffffu, se, 4);
                se += __shfl_xor_sync(0xffffffffu, se, 8);
                se += __shfl_xor_sync(0xffffffffu, se, 16);
                float inv = 1.f / se;
                if ((lane & 1) == 0) w_s[12 + s] = e * inv;
                conf2 = inv;
            }

            // conf softmax (all lanes, redundant)
            float mm = fmaxf(conf0, fmaxf(conf1, conf2));
            float e0 = __expf(conf0 - mm), e1 = __expf(conf1 - mm), e2 = __expf(conf2 - mm);
            float cinv = 1.f / (e0 + e1 + e2);
            float c0 = e0 * cinv, c1 = e1 * cinv, c2 = e2 * cinv;
            if (lane == 0) {
                c_s[r * 3]     = c0;
                c_s[r * 3 + 1] = c1;
                c_s[r * 3 + 2] = c2;
            }
            __syncwarp();

            // retrieved (scaled by c), pair-packed into rvp
            int pbase = (r >> 1) * 224, sub = r & 1;
            {
                float w0 = w_s[0], w1 = w_s[1], w2 = w_s[2], w3 = w_s[3];
                #pragma unroll
                for (int jj = 0; jj < 2; jj++) {
                    int j = lane + jj * 32;
                    float a = w0 * mem0[j] + w1 * mem0[65 + j]
                            + w2 * mem0[130 + j] + w3 * mem0[195 + j];
                    rvp[pbase + j * 2 + sub] = c0 * a;
                }
            }
            {
                float a = 0.f;
                #pragma unroll
                for (int s2 = 0; s2 < 8; s2++) a += w_s[4 + s2] * mem1[s2 * 33 + lane];
                rvp[pbase + (64 + lane) * 2 + sub] = c1 * a;
            }
            if (lane < 16) {
                float a = 0.f;
                #pragma unroll
                for (int s2 = 0; s2 < 16; s2++) a += w_s[12 + s2] * mem2[s2 * 17 + lane];
                rvp[pbase + (96 + lane) * 2 + sub] = c2 * a;
            }
            __syncwarp();
        }

        // ---- step F: up-proj (j-outer, broadcast rvp hoisted) ----
        {
            u64 cp0[3], cp1[3];
            #pragma unroll
            for (int i = 0; i < 3; i++) {
                cp0[i] = pack2(c_s[i],     c_s[3 + i]);
                cp1[i] = pack2(c_s[6 + i], c_s[9 + i]);
            }
            const int h0 = lane, h1 = lane + 32;
            u64 a00 = 0, a01 = 0, a10 = 0, a11 = 0;
            #pragma unroll
            for (int i = 0; i < 3; i++) {
                float b0v = bu_s[i * 64 + h0];
                float b1v = bu_s[i * 64 + h1];
                u64 bb0 = pack2(b0v, b0v), bb1 = pack2(b1v, b1v);
                a00 = fma2(cp0[i], bb0, a00);
                a01 = fma2(cp1[i], bb0, a01);
                a10 = fma2(cp0[i], bb1, a10);
                a11 = fma2(cp1[i], bb1, a11);
            }
            const float* wr0 = &Wu_s[h0 * 113];
            const float* wr1 = &Wu_s[h1 * 113];
            #pragma unroll 4
            for (int j = 0; j < 112; j++) {
                u64 rv0 = *(const u64*)&rvp[j * 2];
                u64 rv1 = *(const u64*)&rvp[224 + j * 2];
                float w0 = wr0[j], w1 = wr1[j];
                u64 ww0 = pack2(w0, w0), ww1 = pack2(w1, w1);
                a00 = fma2(ww0, rv0, a00);
                a01 = fma2(ww0, rv1, a01);
                a10 = fma2(ww1, rv0, a10);
                a11 = fma2(ww1, rv1, a11);
            }
            *(u64*)&hidp[h0 * 2]       = a00;
            *(u64*)&hidp[128 + h0 * 2] = a01;
            *(u64*)&hidp[h1 * 2]       = a10;
            *(u64*)&hidp[128 + h1 * 2] = a11;
        }
        __syncwarp();

        // ---- step G: classifier (h-outer, broadcast hidp hoisted) + store ----
        {
            const int o0 = lane, o1 = lane + 32;
            float bc0 = bc_s[o0], bc1 = bc_s[o1];
            u64 a00 = pack2(bc0, bc0), a01 = pack2(bc0, bc0);
            u64 a10 = pack2(bc1, bc1), a11 = pack2(bc1, bc1);
            const float* wc0 = &Wc_s[o0 * 65];
            const float* wc1 = &Wc_s[o1 * 65];
            #pragma unroll 4
            for (int h = 0; h < 64; h++) {
                u64 hd0 = *(const u64*)&hidp[h * 2];
                u64 hd1 = *(const u64*)&hidp[128 + h * 2];
                float w0 = wc0[h], w1 = wc1[h];
                u64 ww0 = pack2(w0, w0), ww1 = pack2(w1, w1);
                a00 = fma2(ww0, hd0, a00);
                a01 = fma2(ww0, hd1, a01);
                a10 = fma2(ww1, hd0, a10);
                a11 = fma2(ww1, hd1, a11);
            }
            float r0o0, r1o0, r2o0, r3o0, r0o1, r1o1, r2o1, r3o1;
            unpack2(a00, r0o0, r1o0);
            unpack2(a01, r2o0, r3o0);
            unpack2(a10, r0o1, r1o1);
            unpack2(a11, r2o1, r3o1);
            if (r0 < nrows) {
                out_g[(size_t)r0 * 64 + o0] = r0o0;
                out_g[(size_t)r0 * 64 + o1] = r0o1;
            }
            if (r0 + 1 < nrows) {
                out_g[(size_t)(r0 + 1) * 64 + o0] = r1o0;
                out_g[(size_t)(r0 + 1) * 64 + o1] = r1o1;
            }
            if (r0 + 2 < nrows) {
                out_g[(size_t)(r0 + 2) * 64 + o0] = r2o0;
                out_g[(size_t)(r0 + 2) * 64 + o1] = r2o1;
            }
            if (r0 + 3 < nrows) {
                out_g[(size_t)(r0 + 3) * 64 + o0] = r3o0;
                out_g[(size_t)(r0 + 3) * 64 + o1] = r3o1;
            }
        }
        __syncwarp();
    }
}

extern "C" void kernel_launch(void* const* d_in, const int* in_sizes, int n_in,
                              void* d_out, int out_size) {
    // metadata order (setup_inputs insertion order — per-tier INTERLEAVED):
    // 0:query_h 1:mem0 2:mem1 3:mem2
    // 4:Wp0 5:bp0 6:Wu0 7:bu0  8:Wp1 9:bp1 10:Wu1 11:bu1
    // 12:Wp2 13:bp2 14:Wu2 15:bu2  16:Wc 17:bc
    const float* q   = (const float*)d_in[0];
    const float* m0  = (const float*)d_in[1];
    const float* m1  = (const float*)d_in[2];
    const float* m2  = (const float*)d_in[3];
    const float* Wp0 = (const float*)d_in[4];
    const float* bp0 = (const float*)d_in[5];
    const float* Wu0 = (const float*)d_in[6];
    const float* bu0 = (const float*)d_in[7];
    const float* Wp1 = (const float*)d_in[8];
    const float* bp1 = (const float*)d_in[9];
    const float* Wu1 = (const float*)d_in[10];
    const float* bu1 = (const float*)d_in[11];
    const float* Wp2 = (const float*)d_in[12];
    const float* bp2 = (const float*)d_in[13];
    const float* Wu2 = (const float*)d_in[14];
    const float* bu2 = (const float*)d_in[15];
    const float* Wc  = (const float*)d_in[16];
    const float* bc  = (const float*)d_in[17];
    float* out = (float*)d_out;

    int nrows = in_sizes[0] / 64;

    cudaFuncSetAttribute(retrieval_kernel,
                         cudaFuncAttributeMaxDynamicSharedMemorySize, SMEM_BYTES);

    retrieval_kernel<<<NB, NTHR, SMEM_BYTES>>>(
        q, m0, m1, m2,
        Wp0, bp0, Wp1, bp1, Wp2, bp2,
        Wu0, bu0, Wu1, bu1, Wu2, bu2,
        Wc, bc, out, nrows);
}

// round 12
// speedup vs baseline: 3.5461x; 1.8230x over previous
#include <cuda_runtime.h>
#include <cstdint>
#include <cstddef>

// ---------------------------------------------------------------------------
// SimultaneousRetrievalModel on GB300 (sm_103a)
// R12: classifier fused into up-proj via precomputed Fu = Wc@[Wu_cat|bu_i]
// (separate tiny launch -> __device__ scratch). Step G + hidp eliminated.
// Occupancy 12 -> 16 warps/CTA (smem 196 KB). Everything else per R11:
// coalesced LDG.128 mem staging, shfl-fused softmax, f32x2 packed FMA.
// ---------------------------------------------------------------------------

#define WARPS 16
#define NTHR  (WARPS * 32)
#define NB    152

typedef unsigned long long u64;

__device__ __forceinline__ u64 pack2(float lo, float hi) {
    u64 r; asm("mov.b64 %0, {%1, %2};" : "=l"(r) : "f"(lo), "f"(hi)); return r;
}
__device__ __forceinline__ void unpack2(u64 v, float& lo, float& hi) {
    asm("mov.b64 {%0, %1}, %2;" : "=f"(lo), "=f"(hi) : "l"(v));
}
__device__ __forceinline__ u64 fma2(u64 a, u64 b, u64 c) {
    u64 d; asm("fma.rn.f32x2 %0, %1, %2, %3;" : "=l"(d) : "l"(a), "l"(b), "l"(c)); return d;
}

// Fused up-proj+classifier weights: [64][115] compact
__device__ float g_Fu[64 * 115];

__global__ void precompute_fu(const float* __restrict__ Wc,
                              const float* __restrict__ Wu0,
                              const float* __restrict__ Wu1,
                              const float* __restrict__ Wu2,
                              const float* __restrict__ bu0,
                              const float* __restrict__ bu1,
                              const float* __restrict__ bu2) {
    __shared__ float wc_row[64];
    int o = blockIdx.x;       // 64 blocks
    int j = threadIdx.x;      // 128 threads
    if (j < 64) wc_row[j] = Wc[o * 64 + j];
    __syncthreads();
    if (j < 115) {
        float s = 0.f;
        if (j < 64) {
            for (int h = 0; h < 64; h++) s += wc_row[h] * Wu0[h * 64 + j];
        } else if (j < 96) {
            int jj = j - 64;
            for (int h = 0; h < 64; h++) s += wc_row[h] * Wu1[h * 32 + jj];
        } else if (j < 112) {
            int jj = j - 96;
            for (int h = 0; h < 64; h++) s += wc_row[h] * Wu2[h * 16 + jj];
        } else {
            const float* bu = (j == 112) ? bu0 : (j == 113) ? bu1 : bu2;
            for (int h = 0; h < 64; h++) s += wc_row[h] * bu[h];
        }
        g_Fu[o * 115 + j] = s;
    }
}

// ---- block-shared weights (float offsets) ----
#define OFF_WP   0        // [112][65] rows pre-scaled by 1/sqrt(dim)
#define OFF_BP   7280     // [112] pre-scaled
#define OFF_FU   7392     // [64][117] Fu (odd-ish stride 117, conflict-free)
#define OFF_BC   14880    // [64]
#define OFF_WARP 14944

// ---- per-warp scratch (float offsets within warp region) ----
#define S_QT   0        // [64][6]  q transposed                              384
#define S_QP   384      // [4][112] down-projected queries                    448
#define S_M0   832      // [4][65]  tier0 mem (padded)                        264
#define S_M1   1096     // [8][33]  tier1 mem                                 264
#define S_M2   1360     // [16][17] tier2 mem                                 272
#define S_W    1632     // [28] tier softmax weights (current row)             32
#define S_RVP  1664     // [2][116][2] rv_ext pair-packed (8B aligned)        464
#define W_STRIDE 2128

#define SMEM_FLOATS (OFF_WARP + WARPS * W_STRIDE)
#define SMEM_BYTES  (SMEM_FLOATS * 4)

__global__ void __launch_bounds__(NTHR, 1) retrieval_kernel(
    const float* __restrict__ q_g,
    const float* __restrict__ m0_g,
    const float* __restrict__ m1_g,
    const float* __restrict__ m2_g,
    const float* __restrict__ Wp0, const float* __restrict__ bp0,
    const float* __restrict__ Wp1, const float* __restrict__ bp1,
    const float* __restrict__ Wp2, const float* __restrict__ bp2,
    const float* __restrict__ bc_g,
    float* __restrict__ out_g,
    int nrows)
{
    extern __shared__ float sm[];
    const int tid  = threadIdx.x;
    const int wid  = tid >> 5;
    const int lane = tid & 31;

    // ---------------- stage weights (once per block) ----------------
    {
        const float s0 = 0.125f;                  // 1/sqrt(64)
        const float s1 = 0.17677669529663687f;    // 1/sqrt(32)
        const float s2 = 0.25f;                   // 1/sqrt(16)
        for (int idx = tid; idx < 112 * 64; idx += NTHR) {
            int j = idx >> 6, h = idx & 63;
            float v;
            if (j < 64)      v = Wp0[j * 64 + h] * s0;
            else if (j < 96) v = Wp1[(j - 64) * 64 + h] * s1;
            else             v = Wp2[(j - 96) * 64 + h] * s2;
            sm[OFF_WP + j * 65 + h] = v;
        }
        for (int j = tid; j < 112; j += NTHR) {
            float v;
            if (j < 64)      v = bp0[j] * s0;
            else if (j < 96) v = bp1[j - 64] * s1;
            else             v = bp2[j - 96] * s2;
            sm[OFF_BP + j] = v;
        }
        for (int idx = tid; idx < 64 * 115; idx += NTHR) {
            int o = idx / 115, j = idx - o * 115;
            sm[OFF_FU + o * 117 + j] = g_Fu[idx];
        }
        for (int idx = tid; idx < 64; idx += NTHR) sm[OFF_BC + idx] = bc_g[idx];
    }
    __syncthreads();

    float* wbase = sm + OFF_WARP + wid * W_STRIDE;
    float* qt    = wbase + S_QT;
    float* qp_s  = wbase + S_QP;
    float* mem0  = wbase + S_M0;
    float* mem1  = wbase + S_M1;
    float* mem2  = wbase + S_M2;
    float* w_s   = wbase + S_W;
    float* rvp   = wbase + S_RVP;

    const float* Wp_s = sm + OFF_WP;
    const float* bp_s = sm + OFF_BP;
    const float* Fu_s = sm + OFF_FU;
    const float* bc_s = sm + OFF_BC;

    const int gw = blockIdx.x * WARPS + wid;
    const int ngroups = (nrows + 3) >> 2;
    const int gstride = gridDim.x * WARPS;

    for (int g = gw; g < ngroups; g += gstride) {
        const int r0 = g * 4;

        // ---- load q for 4 rows, transposed: qt[h*6 + r] ----
        #pragma unroll
        for (int r = 0; r < 4; r++) {
            int row = min(r0 + r, nrows - 1);
            float v1 = q_g[(size_t)row * 64 + lane];
            float v2 = q_g[(size_t)row * 64 + lane + 32];
            qt[lane * 6 + r]        = v1;
            qt[(lane + 32) * 6 + r] = v2;
        }
        __syncwarp();

        // ---- step A: down-proj, qp[j] = scaled(q.Wp^T + bp) ----
        {
            int j3 = (lane < 16) ? (lane + 96) : (lane + 64);  // dup lanes>=16
            int js[4] = { lane, lane + 32, lane + 64, j3 };
            u64 aA[4], aB[4];   // pair (row0,row1) / (row2,row3)
            #pragma unroll
            for (int k = 0; k < 4; k++) {
                float b = bp_s[js[k]];
                aA[k] = pack2(b, b);
                aB[k] = pack2(b, b);
            }
            #pragma unroll 4
            for (int h = 0; h < 64; h++) {
                u64 qa = *(const u64*)&qt[h * 6];       // (row0,row1)
                u64 qb = *(const u64*)&qt[h * 6 + 2];   // (row2,row3)
                #pragma unroll
                for (int k = 0; k < 4; k++) {
                    float w = Wp_s[js[k] * 65 + h];
                    u64 ww = pack2(w, w);
                    aA[k] = fma2(ww, qa, aA[k]);
                    aB[k] = fma2(ww, qb, aB[k]);
                }
            }
            #pragma unroll
            for (int k = 0; k < 4; k++) {
                if (k == 3 && lane >= 16) break;
                float v0, v1, v2, v3;
                unpack2(aA[k], v0, v1);
                unpack2(aB[k], v2, v3);
                qp_s[0 * 112 + js[k]] = v0;
                qp_s[1 * 112 + js[k]] = v1;
                qp_s[2 * 112 + js[k]] = v2;
                qp_s[3 * 112 + js[k]] = v3;
            }
        }
        __syncwarp();

        // ---- steps B-E: sequential rows; mem staged once, coalesced ----
        for (int r = 0; r < 4; r++) {
            int row = min(r0 + r, nrows - 1);

            // stage 3 tiles (256 floats each) via LDG.128, padded smem
            const float4* f0 = (const float4*)(m0_g + (size_t)row * 256);
            const float4* f1 = (const float4*)(m1_g + (size_t)row * 256);
            const float4* f2 = (const float4*)(m2_g + (size_t)row * 256);
            #pragma unroll
            for (int k = 0; k < 2; k++) {
                int e4 = k * 32 + lane;
                float4 v;
                float* dst;
                v = f0[e4];
                dst = &mem0[(e4 >> 4) * 65 + (e4 & 15) * 4];
                dst[0] = v.x; dst[1] = v.y; dst[2] = v.z; dst[3] = v.w;
                v = f1[e4];
                dst = &mem1[(e4 >> 3) * 33 + (e4 & 7) * 4];
                dst[0] = v.x; dst[1] = v.y; dst[2] = v.z; dst[3] = v.w;
                v = f2[e4];
                dst = &mem2[(e4 >> 2) * 17 + (e4 & 3) * 4];
                dst[0] = v.x; dst[1] = v.y; dst[2] = v.z; dst[3] = v.w;
            }
            __syncwarp();

            const float* qpr = qp_s + r * 112;
            float conf0, conf1, conf2;

            // tier0: 4 slots x dim64; lane = (s<<3)|hg
            {
                int s = lane >> 3, hg = lane & 7;
                const float* mrow = &mem0[s * 65 + hg * 8];
                const float* qph  = &qpr[hg * 8];
                float acc = 0.f;
                #pragma unroll
                for (int k = 0; k < 8; k++) acc += mrow[k] * qph[k];
                acc += __shfl_xor_sync(0xffffffffu, acc, 1);
                acc += __shfl_xor_sync(0xffffffffu, acc, 2);
                acc += __shfl_xor_sync(0xffffffffu, acc, 4);
                float mx = acc;
                mx = fmaxf(mx, __shfl_xor_sync(0xffffffffu, mx, 8));
                mx = fmaxf(mx, __shfl_xor_sync(0xffffffffu, mx, 16));
                float e = __expf(acc - mx);
                float se = e;
                se += __shfl_xor_sync(0xffffffffu, se, 8);
                se += __shfl_xor_sync(0xffffffffu, se, 16);
                float inv = 1.f / se;
                if ((lane & 7) == 0) w_s[s] = e * inv;
                conf0 = inv;
            }
            // tier1: 8 slots x dim32; lane = (s<<2)|hg
            {
                int s = lane >> 2, hg = lane & 3;
                const float* mrow = &mem1[s * 33 + hg * 8];
                const float* qph  = &qpr[64 + hg * 8];
                float acc = 0.f;
                #pragma unroll
                for (int k = 0; k < 8; k++) acc += mrow[k] * qph[k];
                acc += __shfl_xor_sync(0xffffffffu, acc, 1);
                acc += __shfl_xor_sync(0xffffffffu, acc, 2);
                float mx = acc;
                mx = fmaxf(mx, __shfl_xor_sync(0xffffffffu, mx, 4));
                mx = fmaxf(mx, __shfl_xor_sync(0xffffffffu, mx, 8));
                mx = fmaxf(mx, __shfl_xor_sync(0xffffffffu, mx, 16));
                float e = __expf(acc - mx);
                float se = e;
                se += __shfl_xor_sync(0xffffffffu, se, 4);
                se += __shfl_xor_sync(0xffffffffu, se, 8);
                se += __shfl_xor_sync(0xffffffffu, se, 16);
                float inv = 1.f / se;
                if ((lane & 3) == 0) w_s[4 + s] = e * inv;
                conf1 = inv;
            }
            // tier2: 16 slots x dim16; lane = (s<<1)|hg
            {
                int s = lane >> 1, hg = lane & 1;
                const float* mrow = &mem2[s * 17 + hg * 8];
                const float* qph  = &qpr[96 + hg * 8];
                float acc = 0.f;
                #pragma unroll
                for (int k = 0; k < 8; k++) acc += mrow[k] * qph[k];
                acc += __shfl_xor_sync(0xffffffffu, acc, 1);
                float mx = acc;
                mx = fmaxf(mx, __shfl_xor_sync(0xffffffffu, mx, 2));
                mx = fmaxf(mx, __shfl_xor_sync(0xffffffffu, mx, 4));
                mx = fmaxf(mx, __shfl_xor_sync(0xffffffffu, mx, 8));
                mx = fmaxf(mx, __shfl_xor_sync(0xffffffffu, mx, 16));
                float e = __expf(acc - mx);
                float se = e;
                se += __shfl_xor_sync(0xffffffffu, se, 2);
                se += __shfl_xor_sync(0xffffffffu, se, 4);
                se += __shfl_xor_sync(0xffffffffu, se, 8);
                se += __shfl_xor_sync(0xffffffffu, se, 16);
                float inv = 1.f / se;
                if ((lane & 1) == 0) w_s[12 + s] = e * inv;
                conf2 = inv;
            }

            // conf softmax (all lanes, redundant)
            float mm = fmaxf(conf0, fmaxf(conf1, conf2));
            float e0 = __expf(conf0 - mm), e1 = __expf(conf1 - mm), e2 = __expf(conf2 - mm);
            float cinv = 1.f / (e0 + e1 + e2);
            float c0 = e0 * cinv, c1 = e1 * cinv, c2 = e2 * cinv;
            __syncwarp();

            // rv_ext (scaled by c), pair-packed into rvp; extras c0..c2 at j=112..114
            int pbase = (r >> 1) * 232, sub = r & 1;
            {
                float w0 = w_s[0], w1 = w_s[1], w2 = w_s[2], w3 = w_s[3];
                #pragma unroll
                for (int jj = 0; jj < 2; jj++) {
                    int j = lane + jj * 32;
                    float a = w0 * mem0[j] + w1 * mem0[65 + j]
                            + w2 * mem0[130 + j] + w3 * mem0[195 + j];
                    rvp[pbase + j * 2 + sub] = c0 * a;
                }
            }
            {
                float a = 0.f;
                #pragma unroll
                for (int s2 = 0; s2 < 8; s2++) a += w_s[4 + s2] * mem1[s2 * 33 + lane];
                rvp[pbase + (64 + lane) * 2 + sub] = c1 * a;
            }
            if (lane < 16) {
                float a = 0.f;
                #pragma unroll
                for (int s2 = 0; s2 < 16; s2++) a += w_s[12 + s2] * mem2[s2 * 17 + lane];
                rvp[pbase + (96 + lane) * 2 + sub] = c2 * a;
            }
            if (lane == 0) {
                rvp[pbase + 224 + sub] = c0;   // j=112
                rvp[pbase + 226 + sub] = c1;   // j=113
                rvp[pbase + 228 + sub] = c2;   // j=114
            }
            __syncwarp();
        }

        // ---- step F': fused up-proj+classifier, write out directly ----
        {
            const int o0 = lane, o1 = lane + 32;
            float bc0 = bc_s[o0], bc1 = bc_s[o1];
            u64 a00 = pack2(bc0, bc0), a01 = pack2(bc0, bc0);   // o0: (r0,r1)/(r2,r3)
            u64 a10 = pack2(bc1, bc1), a11 = pack2(bc1, bc1);   // o1
            const float* f0r = &Fu_s[o0 * 117];
            const float* f1r = &Fu_s[o1 * 117];
            #pragma unroll 5
            for (int j = 0; j < 115; j++) {
                u64 rv0 = *(const u64*)&rvp[j * 2];
                u64 rv1 = *(const u64*)&rvp[232 + j * 2];
                float w0 = f0r[j], w1 = f1r[j];
                u64 ww0 = pack2(w0, w0), ww1 = pack2(w1, w1);
                a00 = fma2(ww0, rv0, a00);
                a01 = fma2(ww0, rv1, a01);
                a10 = fma2(ww1, rv0, a10);
                a11 = fma2(ww1, rv1, a11);
            }
            float r0o0, r1o0, r2o0, r3o0, r0o1, r1o1, r2o1, r3o1;
            unpack2(a00, r0o0, r1o0);
            unpack2(a01, r2o0, r3o0);
            unpack2(a10, r0o1, r1o1);
            unpack2(a11, r2o1, r3o1);
            if (r0 < nrows) {
                out_g[(size_t)r0 * 64 + o0] = r0o0;
                out_g[(size_t)r0 * 64 + o1] = r0o1;
            }
            if (r0 + 1 < nrows) {
                out_g[(size_t)(r0 + 1) * 64 + o0] = r1o0;
                out_g[(size_t)(r0 + 1) * 64 + o1] = r1o1;
            }
            if (r0 + 2 < nrows) {
                out_g[(size_t)(r0 + 2) * 64 + o0] = r2o0;
                out_g[(size_t)(r0 + 2) * 64 + o1] = r2o1;
            }
            if (r0 + 3 < nrows) {
                out_g[(size_t)(r0 + 3) * 64 + o0] = r3o0;
                out_g[(size_t)(r0 + 3) * 64 + o1] = r3o1;
            }
        }
        __syncwarp();
    }
}

extern "C" void kernel_launch(void* const* d_in, const int* in_sizes, int n_in,
                              void* d_out, int out_size) {
    // metadata order (setup_inputs insertion order — per-tier INTERLEAVED):
    // 0:query_h 1:mem0 2:mem1 3:mem2
    // 4:Wp0 5:bp0 6:Wu0 7:bu0  8:Wp1 9:bp1 10:Wu1 11:bu1
    // 12:Wp2 13:bp2 14:Wu2 15:bu2  16:Wc 17:bc
    const float* q   = (const float*)d_in[0];
    const float* m0  = (const float*)d_in[1];
    const float* m1  = (const float*)d_in[2];
    const float* m2  = (const float*)d_in[3];
    const float* Wp0 = (const float*)d_in[4];
    const float* bp0 = (const float*)d_in[5];
    const float* Wu0 = (const float*)d_in[6];
    const float* bu0 = (const float*)d_in[7];
    const float* Wp1 = (const float*)d_in[8];
    const float* bp1 = (const float*)d_in[9];
    const float* Wu1 = (const float*)d_in[10];
    const float* bu1 = (const float*)d_in[11];
    const float* Wp2 = (const float*)d_in[12];
    const float* bp2 = (const float*)d_in[13];
    const float* Wu2 = (const float*)d_in[14];
    const float* bu2 = (const float*)d_in[15];
    const float* Wc  = (const float*)d_in[16];
    const float* bc  = (const float*)d_in[17];
    float* out = (float*)d_out;

    int nrows = in_sizes[0] / 64;

    cudaFuncSetAttribute(retrieval_kernel,
                         cudaFuncAttributeMaxDynamicSharedMemorySize, SMEM_BYTES);

    precompute_fu<<<64, 128>>>(Wc, Wu0, Wu1, Wu2, bu0, bu1, bu2);

    retrieval_kernel<<<NB, NTHR, SMEM_BYTES>>>(
        q, m0, m1, m2,
        Wp0, bp0, Wp1, bp1, Wp2, bp2,
        bc, out, nrows);
}

// round 13
// speedup vs baseline: 4.0088x; 1.1305x over previous
#include <cuda_runtime.h>
#include <cstdint>
#include <cstddef>

// ---------------------------------------------------------------------------
// SimultaneousRetrievalModel on GB300 (sm_103a)
// R13: sims operands loaded straight into registers (lane l owns global floats
// [8l,8l+8) for ALL tiers -> 2x LDG.128/tier, no sims LDS); staging STS now
// conflict-free per-lane runs; qt/rvp smem aliased -> 18 warps/CTA (185KB).
// Fu fusion + f32x2 packed FMA as R12.
// ---------------------------------------------------------------------------

#define WARPS 18
#define NTHR  (WARPS * 32)
#define NB    152

typedef unsigned long long u64;

__device__ __forceinline__ u64 pack2(float lo, float hi) {
    u64 r; asm("mov.b64 %0, {%1, %2};" : "=l"(r) : "f"(lo), "f"(hi)); return r;
}
__device__ __forceinline__ void unpack2(u64 v, float& lo, float& hi) {
    asm("mov.b64 {%0, %1}, %2;" : "=f"(lo), "=f"(hi) : "l"(v));
}
__device__ __forceinline__ u64 fma2(u64 a, u64 b, u64 c) {
    u64 d; asm("fma.rn.f32x2 %0, %1, %2, %3;" : "=l"(d) : "l"(a), "l"(b), "l"(c)); return d;
}

// Fused up-proj+classifier weights: [64][115] compact
__device__ float g_Fu[64 * 115];

__global__ void precompute_fu(const float* __restrict__ Wc,
                              const float* __restrict__ Wu0,
                              const float* __restrict__ Wu1,
                              const float* __restrict__ Wu2,
                              const float* __restrict__ bu0,
                              const float* __restrict__ bu1,
                              const float* __restrict__ bu2) {
    __shared__ float wc_row[64];
    int o = blockIdx.x;       // 64 blocks
    int j = threadIdx.x;      // 128 threads
    if (j < 64) wc_row[j] = Wc[o * 64 + j];
    __syncthreads();
    if (j < 115) {
        float s = 0.f;
        if (j < 64) {
            for (int h = 0; h < 64; h++) s += wc_row[h] * Wu0[h * 64 + j];
        } else if (j < 96) {
            int jj = j - 64;
            for (int h = 0; h < 64; h++) s += wc_row[h] * Wu1[h * 32 + jj];
        } else if (j < 112) {
            int jj = j - 96;
            for (int h = 0; h < 64; h++) s += wc_row[h] * Wu2[h * 16 + jj];
        } else {
            const float* bu = (j == 112) ? bu0 : (j == 113) ? bu1 : bu2;
            for (int h = 0; h < 64; h++) s += wc_row[h] * bu[h];
        }
        g_Fu[o * 115 + j] = s;
    }
}

// ---- block-shared weights (float offsets) ----
#define OFF_WP   0        // [112][65] rows pre-scaled by 1/sqrt(dim)
#define OFF_BP   7280     // [112] pre-scaled
#define OFF_FU   7392     // [64][117]
#define OFF_BC   14880    // [64]
#define OFF_WARP 14944

// ---- per-warp scratch (float offsets within warp region) ----
// S_RVQT: union of qt [64][6]=384 (dead after step A) and rvp [2][116][2]=464
#define S_RVQT 0
#define S_QP   464      // [4][112] = 448
#define S_M0   912      // [4][65]  = 260 (pad 264)
#define S_M1   1176     // [8][33]  = 264
#define S_M2   1440     // [16][17] = 272
#define S_W    1712     // [28] (pad 32)
#define W_STRIDE 1744

#define SMEM_FLOATS (OFF_WARP + WARPS * W_STRIDE)
#define SMEM_BYTES  (SMEM_FLOATS * 4)

__global__ void __launch_bounds__(NTHR, 1) retrieval_kernel(
    const float* __restrict__ q_g,
    const float* __restrict__ m0_g,
    const float* __restrict__ m1_g,
    const float* __restrict__ m2_g,
    const float* __restrict__ Wp0, const float* __restrict__ bp0,
    const float* __restrict__ Wp1, const float* __restrict__ bp1,
    const float* __restrict__ Wp2, const float* __restrict__ bp2,
    const float* __restrict__ bc_g,
    float* __restrict__ out_g,
    int nrows)
{
    extern __shared__ float sm[];
    const int tid  = threadIdx.x;
    const int wid  = tid >> 5;
    const int lane = tid & 31;

    // ---------------- stage weights (once per block) ----------------
    {
        const float s0 = 0.125f;                  // 1/sqrt(64)
        const float s1 = 0.17677669529663687f;    // 1/sqrt(32)
        const float s2 = 0.25f;                   // 1/sqrt(16)
        for (int idx = tid; idx < 112 * 64; idx += NTHR) {
            int j = idx >> 6, h = idx & 63;
            float v;
            if (j < 64)      v = Wp0[j * 64 + h] * s0;
            else if (j < 96) v = Wp1[(j - 64) * 64 + h] * s1;
            else             v = Wp2[(j - 96) * 64 + h] * s2;
            sm[OFF_WP + j * 65 + h] = v;
        }
        for (int j = tid; j < 112; j += NTHR) {
            float v;
            if (j < 64)      v = bp0[j] * s0;
            else if (j < 96) v = bp1[j - 64] * s1;
            else             v = bp2[j - 96] * s2;
            sm[OFF_BP + j] = v;
        }
        for (int idx = tid; idx < 64 * 115; idx += NTHR) {
            int o = idx / 115, j = idx - o * 115;
            sm[OFF_FU + o * 117 + j] = g_Fu[idx];
        }
        for (int idx = tid; idx < 64; idx += NTHR) sm[OFF_BC + idx] = bc_g[idx];
    }
    __syncthreads();

    float* wbase = sm + OFF_WARP + wid * W_STRIDE;
    float* qt    = wbase + S_RVQT;   // step A only
    float* rvp   = wbase + S_RVQT;   // steps B-F (aliases qt)
    float* qp_s  = wbase + S_QP;
    float* mem0  = wbase + S_M0;
    float* mem1  = wbase + S_M1;
    float* mem2  = wbase + S_M2;
    float* w_s   = wbase + S_W;

    const float* Wp_s = sm + OFF_WP;
    const float* bp_s = sm + OFF_BP;
    const float* Fu_s = sm + OFF_FU;
    const float* bc_s = sm + OFF_BC;

    const int gw = blockIdx.x * WARPS + wid;
    const int ngroups = (nrows + 3) >> 2;
    const int gstride = gridDim.x * WARPS;

    for (int g = gw; g < ngroups; g += gstride) {
        const int r0 = g * 4;

        // ---- load q for 4 rows, transposed: qt[h*6 + r] ----
        #pragma unroll
        for (int r = 0; r < 4; r++) {
            int row = min(r0 + r, nrows - 1);
            float v1 = q_g[(size_t)row * 64 + lane];
            float v2 = q_g[(size_t)row * 64 + lane + 32];
            qt[lane * 6 + r]        = v1;
            qt[(lane + 32) * 6 + r] = v2;
        }
        __syncwarp();

        // ---- step A: down-proj, qp[j] = scaled(q.Wp^T + bp) ----
        {
            int j3 = (lane < 16) ? (lane + 96) : (lane + 64);  // dup lanes>=16
            int js[4] = { lane, lane + 32, lane + 64, j3 };
            u64 aA[4], aB[4];   // pair (row0,row1) / (row2,row3)
            #pragma unroll
            for (int k = 0; k < 4; k++) {
                float b = bp_s[js[k]];
                aA[k] = pack2(b, b);
                aB[k] = pack2(b, b);
            }
            #pragma unroll 4
            for (int h = 0; h < 64; h++) {
                u64 qa = *(const u64*)&qt[h * 6];       // (row0,row1)
                u64 qb = *(const u64*)&qt[h * 6 + 2];   // (row2,row3)
                #pragma unroll
                for (int k = 0; k < 4; k++) {
                    float w = Wp_s[js[k] * 65 + h];
                    u64 ww = pack2(w, w);
                    aA[k] = fma2(ww, qa, aA[k]);
                    aB[k] = fma2(ww, qb, aB[k]);
                }
            }
            #pragma unroll
            for (int k = 0; k < 4; k++) {
                if (k == 3 && lane >= 16) break;
                float v0, v1, v2, v3;
                unpack2(aA[k], v0, v1);
                unpack2(aB[k], v2, v3);
                qp_s[0 * 112 + js[k]] = v0;
                qp_s[1 * 112 + js[k]] = v1;
                qp_s[2 * 112 + js[k]] = v2;
                qp_s[3 * 112 + js[k]] = v3;
            }
        }
        __syncwarp();   // qt no longer needed; rvp may now overwrite it

        // ---- steps B-E: per row; sims from REGISTERS, staging for retrieved ----
        for (int r = 0; r < 4; r++) {
            int row = min(r0 + r, nrows - 1);

            // each lane loads ITS sims chunk: global floats [8*lane, 8*lane+8)
            const float4* f0 = (const float4*)(m0_g + (size_t)row * 256);
            const float4* f1 = (const float4*)(m1_g + (size_t)row * 256);
            const float4* f2 = (const float4*)(m2_g + (size_t)row * 256);
            float ch0[8], ch1[8], ch2[8];
            *(float4*)&ch0[0] = f0[2 * lane];
            *(float4*)&ch0[4] = f0[2 * lane + 1];
            *(float4*)&ch1[0] = f1[2 * lane];
            *(float4*)&ch1[4] = f1[2 * lane + 1];
            *(float4*)&ch2[0] = f2[2 * lane];
            *(float4*)&ch2[4] = f2[2 * lane + 1];

            const float* qpr = qp_s + r * 112;
            float conf0, conf1, conf2;

            // tier0: 4 slots x dim64; lane = (s<<3)|hg, chunk = mem0[s][hg*8..+8]
            {
                int s = lane >> 3, hg = lane & 7;
                float qph[8];
                *(float4*)&qph[0] = *(const float4*)&qpr[hg * 8];
                *(float4*)&qph[4] = *(const float4*)&qpr[hg * 8 + 4];
                float acc = 0.f;
                #pragma unroll
                for (int k = 0; k < 8; k++) acc += ch0[k] * qph[k];
                acc += __shfl_xor_sync(0xffffffffu, acc, 1);
                acc += __shfl_xor_sync(0xffffffffu, acc, 2);
                acc += __shfl_xor_sync(0xffffffffu, acc, 4);
                float mx = acc;
                mx = fmaxf(mx, __shfl_xor_sync(0xffffffffu, mx, 8));
                mx = fmaxf(mx, __shfl_xor_sync(0xffffffffu, mx, 16));
                float e = __expf(acc - mx);
                float se = e;
                se += __shfl_xor_sync(0xffffffffu, se, 8);
                se += __shfl_xor_sync(0xffffffffu, se, 16);
                float inv = 1.f / se;
                if ((lane & 7) == 0) w_s[s] = e * inv;
                conf0 = inv;
            }
            // tier1: 8 slots x dim32; lane = (s<<2)|hg, chunk = mem1[s][hg*8..+8]
            {
                int s = lane >> 2, hg = lane & 3;
                float qph[8];
                *(float4*)&qph[0] = *(const float4*)&qpr[64 + hg * 8];
                *(float4*)&qph[4] = *(const float4*)&qpr[64 + hg * 8 + 4];
                float acc = 0.f;
                #pragma unroll
                for (int k = 0; k < 8; k++) acc += ch1[k] * qph[k];
                acc += __shfl_xor_sync(0xffffffffu, acc, 1);
                acc += __shfl_xor_sync(0xffffffffu, acc, 2);
                float mx = acc;
                mx = fmaxf(mx, __shfl_xor_sync(0xffffffffu, mx, 4));
                mx = fmaxf(mx, __shfl_xor_sync(0xffffffffu, mx, 8));
                mx = fmaxf(mx, __shfl_xor_sync(0xffffffffu, mx, 16));
                float e = __expf(acc - mx);
                float se = e;
                se += __shfl_xor_sync(0xffffffffu, se, 4);
                se += __shfl_xor_sync(0xffffffffu, se, 8);
                se += __shfl_xor_sync(0xffffffffu, se, 16);
                float inv = 1.f / se;
                if ((lane & 3) == 0) w_s[4 + s] = e * inv;
                conf1 = inv;
            }
            // tier2: 16 slots x dim16; lane = (s<<1)|hg, chunk = mem2[s][hg*8..+8]
            {
                int s = lane >> 1, hg = lane & 1;
                float qph[8];
                *(float4*)&qph[0] = *(const float4*)&qpr[96 + hg * 8];
                *(float4*)&qph[4] = *(const float4*)&qpr[96 + hg * 8 + 4];
                float acc = 0.f;
                #pragma unroll
                for (int k = 0; k < 8; k++) acc += ch2[k] * qph[k];
                acc += __shfl_xor_sync(0xffffffffu, acc, 1);
                float mx = acc;
                mx = fmaxf(mx, __shfl_xor_sync(0xffffffffu, mx, 2));
                mx = fmaxf(mx, __shfl_xor_sync(0xffffffffu, mx, 4));
                mx = fmaxf(mx, __shfl_xor_sync(0xffffffffu, mx, 8));
                mx = fmaxf(mx, __shfl_xor_sync(0xffffffffu, mx, 16));
                float e = __expf(acc - mx);
                float se = e;
                se += __shfl_xor_sync(0xffffffffu, se, 2);
                se += __shfl_xor_sync(0xffffffffu, se, 4);
                se += __shfl_xor_sync(0xffffffffu, se, 8);
                se += __shfl_xor_sync(0xffffffffu, se, 16);
                float inv = 1.f / se;
                if ((lane & 1) == 0) w_s[12 + s] = e * inv;
                conf2 = inv;
            }

            // conf softmax (all lanes, redundant)
            float mm = fmaxf(conf0, fmaxf(conf1, conf2));
            float e0 = __expf(conf0 - mm), e1 = __expf(conf1 - mm), e2 = __expf(conf2 - mm);
            float cinv = 1.f / (e0 + e1 + e2);
            float c0 = e0 * cinv, c1 = e1 * cinv, c2 = e2 * cinv;

            // stage chunks into padded smem (conflict-light per-lane runs)
            {
                float* d0 = &mem0[(lane >> 3) * 65 + (lane & 7) * 8];
                float* d1 = &mem1[(lane >> 2) * 33 + (lane & 3) * 8];
                float* d2 = &mem2[(lane >> 1) * 17 + (lane & 1) * 8];
                #pragma unroll
                for (int k = 0; k < 8; k++) d0[k] = ch0[k];
                #pragma unroll
                for (int k = 0; k < 8; k++) d1[k] = ch1[k];
                #pragma unroll
                for (int k = 0; k < 8; k++) d2[k] = ch2[k];
            }
            __syncwarp();

            // retrieved (scaled by c), pair-packed into rvp; c extras at j=112..114
            int pbase = (r >> 1) * 232, sub = r & 1;
            {
                float w0 = w_s[0], w1 = w_s[1], w2 = w_s[2], w3 = w_s[3];
                #pragma unroll
                for (int jj = 0; jj < 2; jj++) {
                    int j = lane + jj * 32;
                    float a = w0 * mem0[j] + w1 * mem0[65 + j]
                            + w2 * mem0[130 + j] + w3 * mem0[195 + j];
                    rvp[pbase + j * 2 + sub] = c0 * a;
                }
            }
            {
                float a = 0.f;
                #pragma unroll
                for (int s2 = 0; s2 < 8; s2++) a += w_s[4 + s2] * mem1[s2 * 33 + lane];
                rvp[pbase + (64 + lane) * 2 + sub] = c1 * a;
            }
            if (lane < 16) {
                float a = 0.f;
                #pragma unroll
                for (int s2 = 0; s2 < 16; s2++) a += w_s[12 + s2] * mem2[s2 * 17 + lane];
                rvp[pbase + (96 + lane) * 2 + sub] = c2 * a;
            }
            if (lane == 0) {
                rvp[pbase + 224 + sub] = c0;   // j=112
                rvp[pbase + 226 + sub] = c1;   // j=113
                rvp[pbase + 228 + sub] = c2;   // j=114
            }
            __syncwarp();
        }

        // ---- step F': fused up-proj+classifier, write out directly ----
        {
            const int o0 = lane, o1 = lane + 32;
            float bc0 = bc_s[o0], bc1 = bc_s[o1];
            u64 a00 = pack2(bc0, bc0), a01 = pack2(bc0, bc0);   // o0: (r0,r1)/(r2,r3)
            u64 a10 = pack2(bc1, bc1), a11 = pack2(bc1, bc1);   // o1
            const float* f0r = &Fu_s[o0 * 117];
            const float* f1r = &Fu_s[o1 * 117];
            #pragma unroll 5
            for (int j = 0; j < 115; j++) {
                u64 rv0 = *(const u64*)&rvp[j * 2];
                u64 rv1 = *(const u64*)&rvp[232 + j * 2];
                float w0 = f0r[j], w1 = f1r[j];
                u64 ww0 = pack2(w0, w0), ww1 = pack2(w1, w1);
                a00 = fma2(ww0, rv0, a00);
                a01 = fma2(ww0, rv1, a01);
                a10 = fma2(ww1, rv0, a10);
                a11 = fma2(ww1, rv1, a11);
            }
            float r0o0, r1o0, r2o0, r3o0, r0o1, r1o1, r2o1, r3o1;
            unpack2(a00, r0o0, r1o0);
            unpack2(a01, r2o0, r3o0);
            unpack2(a10, r0o1, r1o1);
            unpack2(a11, r2o1, r3o1);
            if (r0 < nrows) {
                out_g[(size_t)r0 * 64 + o0] = r0o0;
                out_g[(size_t)r0 * 64 + o1] = r0o1;
            }
            if (r0 + 1 < nrows) {
                out_g[(size_t)(r0 + 1) * 64 + o0] = r1o0;
                out_g[(size_t)(r0 + 1) * 64 + o1] = r1o1;
            }
            if (r0 + 2 < nrows) {
                out_g[(size_t)(r0 + 2) * 64 + o0] = r2o0;
                out_g[(size_t)(r0 + 2) * 64 + o1] = r2o1;
            }
            if (r0 + 3 < nrows) {
                out_g[(size_t)(r0 + 3) * 64 + o0] = r3o0;
                out_g[(size_t)(r0 + 3) * 64 + o1] = r3o1;
            }
        }
        __syncwarp();
    }
}

extern "C" void kernel_launch(void* const* d_in, const int* in_sizes, int n_in,
                              void* d_out, int out_size) {
    // metadata order (setup_inputs insertion order — per-tier INTERLEAVED):
    // 0:query_h 1:mem0 2:mem1 3:mem2
    // 4:Wp0 5:bp0 6:Wu0 7:bu0  8:Wp1 9:bp1 10:Wu1 11:bu1
    // 12:Wp2 13:bp2 14:Wu2 15:bu2  16:Wc 17:bc
    const float* q   = (const float*)d_in[0];
    const float* m0  = (const float*)d_in[1];
    const float* m1  = (const float*)d_in[2];
    const float* m2  = (const float*)d_in[3];
    const float* Wp0 = (const float*)d_in[4];
    const float* bp0 = (const float*)d_in[5];
    const float* Wu0 = (const float*)d_in[6];
    const float* bu0 = (const float*)d_in[7];
    const float* Wp1 = (const float*)d_in[8];
    const float* bp1 = (const float*)d_in[9];
    const float* Wu1 = (const float*)d_in[10];
    const float* bu1 = (const float*)d_in[11];
    const float* Wp2 = (const float*)d_in[12];
    const float* bp2 = (const float*)d_in[13];
    const float* Wu2 = (const float*)d_in[14];
    const float* bu2 = (const float*)d_in[15];
    const float* Wc  = (const float*)d_in[16];
    const float* bc  = (const float*)d_in[17];
    float* out = (float*)d_out;

    int nrows = in_sizes[0] / 64;

    cudaFuncSetAttribute(retrieval_kernel,
                         cudaFuncAttributeMaxDynamicSharedMemorySize, SMEM_BYTES);

    precompute_fu<<<64, 128>>>(Wc, Wu0, Wu1, Wu2, bu0, bu1, bu2);

    retrieval_kernel<<<NB, NTHR, SMEM_BYTES>>>(
        q, m0, m1, m2,
        Wp0, bp0, Wp1, bp1, Wp2, bp2,
        bc, out, nrows);
}